// round 1
// baseline (speedup 1.0000x reference)
#include <cuda_runtime.h>
#include <cstdint>

// Problem constants (fixed by the dataset)
#define NN 20000
#define FF 512
#define DD 256
#define EE 200000
#define LL 3
#define TT 2

// ---------------- device scratch (no allocation allowed) ----------------
__device__ float g_h[NN * DD];      // current layer features
__device__ float g_hp[NN * DD];     // relu(h @ Wpool^T + b)
__device__ float g_neigh[NN * DD];  // segment_max result
__device__ float g_rst[NN * DD];    // pre-layernorm result
__device__ float g_out[NN * DD];    // per-layer etype accumulator

// ---------------- SGEMM: C[M, 256] = A @ B^T (+ A2 @ B2^T) + bias -------
// B is row-major [Nout, K] (so this computes A @ B^T). BM=128,BN=128,BK=16,
// 256 threads, 8x8 microtile per thread.
#define BM 128
#define BN 128
#define BKK 16
#define PAD 4

template <bool RELU, bool DUAL>
__global__ void __launch_bounds__(256, 2)
sgemm_kernel(const float* __restrict__ A0, const float* __restrict__ B0,
             const float* __restrict__ A1, const float* __restrict__ B1,
             const float* __restrict__ bias, float* __restrict__ C,
             int M, int K) {
    __shared__ float As[BKK][BM + PAD];
    __shared__ float Bs[BKK][BN + PAD];

    const int tid = threadIdx.x;
    const int brow = blockIdx.x;
    const int bcol = blockIdx.y;
    const int tx = tid & 15;   // 0..15 -> col group
    const int ty = tid >> 4;   // 0..15 -> row group

    const int lrow = tid >> 2;        // 0..63
    const int lc4  = (tid & 3) * 4;   // 0,4,8,12

    float acc[8][8];
#pragma unroll
    for (int i = 0; i < 8; ++i)
#pragma unroll
        for (int j = 0; j < 8; ++j) acc[i][j] = 0.f;

    const int passes = DUAL ? 2 : 1;
    for (int p = 0; p < passes; ++p) {
        const float* __restrict__ A = (p == 0) ? A0 : A1;
        const float* __restrict__ B = (p == 0) ? B0 : B1;
        for (int k0 = 0; k0 < K; k0 += BKK) {
#pragma unroll
            for (int h = 0; h < 2; ++h) {
                const int r = lrow + h * 64;
                const int gr = brow * BM + r;
                float4 a;
                if (gr < M)
                    a = *(const float4*)(A + (size_t)gr * K + k0 + lc4);
                else
                    a = make_float4(0.f, 0.f, 0.f, 0.f);
                As[lc4 + 0][r] = a.x; As[lc4 + 1][r] = a.y;
                As[lc4 + 2][r] = a.z; As[lc4 + 3][r] = a.w;
                // weight rows are the output columns
                float4 b = *(const float4*)(B + (size_t)(bcol * BN + r) * K + k0 + lc4);
                Bs[lc4 + 0][r] = b.x; Bs[lc4 + 1][r] = b.y;
                Bs[lc4 + 2][r] = b.z; Bs[lc4 + 3][r] = b.w;
            }
            __syncthreads();
#pragma unroll
            for (int k = 0; k < BKK; ++k) {
                float ar[8], br[8];
                *(float4*)(ar)     = *(const float4*)&As[k][ty * 8];
                *(float4*)(ar + 4) = *(const float4*)&As[k][ty * 8 + 4];
                *(float4*)(br)     = *(const float4*)&Bs[k][tx * 8];
                *(float4*)(br + 4) = *(const float4*)&Bs[k][tx * 8 + 4];
#pragma unroll
                for (int i = 0; i < 8; ++i)
#pragma unroll
                    for (int j = 0; j < 8; ++j)
                        acc[i][j] = fmaf(ar[i], br[j], acc[i][j]);
            }
            __syncthreads();
        }
    }

    // epilogue: bias (+relu) and store
    const int Ntot = gridDim.y * BN;
#pragma unroll
    for (int i = 0; i < 8; ++i) {
        const int gr = brow * BM + ty * 8 + i;
        if (gr >= M) continue;
#pragma unroll
        for (int j = 0; j < 8; j += 4) {
            const int gc = bcol * BN + tx * 8 + j;
            float4 bv = *(const float4*)(bias + gc);
            float4 v;
            v.x = acc[i][j + 0] + bv.x;
            v.y = acc[i][j + 1] + bv.y;
            v.z = acc[i][j + 2] + bv.z;
            v.w = acc[i][j + 3] + bv.w;
            if (RELU) {
                v.x = fmaxf(v.x, 0.f); v.y = fmaxf(v.y, 0.f);
                v.z = fmaxf(v.z, 0.f); v.w = fmaxf(v.w, 0.f);
            }
            *(float4*)(C + (size_t)gr * Ntot + gc) = v;
        }
    }
}

// ---------------- scatter-max (segment_max with relu-nonneg trick) ------
// neigh must be pre-zeroed. hp >= 0 (relu), so uint-bit atomicMax is exact,
// and zeros can be skipped.
__global__ void __launch_bounds__(256)
scatter_max_kernel(const int* __restrict__ src, const int* __restrict__ dst,
                   const float* __restrict__ hp, float* __restrict__ neigh,
                   int E) {
    const int idx = blockIdx.x * blockDim.x + threadIdx.x;
    const int total = E * (DD / 4);
    if (idx >= total) return;
    const int e = idx >> 6;        // DD/4 = 64 chunks per edge
    const int c4 = idx & 63;
    const int s = __ldg(src + e);
    const int d = __ldg(dst + e);
    float4 v = *(const float4*)(hp + (size_t)s * DD + c4 * 4);
    unsigned* base = (unsigned*)(neigh + (size_t)d * DD + c4 * 4);
    if (v.x > 0.f) atomicMax(base + 0, __float_as_uint(v.x));
    if (v.y > 0.f) atomicMax(base + 1, __float_as_uint(v.y));
    if (v.z > 0.f) atomicMax(base + 2, __float_as_uint(v.z));
    if (v.w > 0.f) atomicMax(base + 3, __float_as_uint(v.w));
}

// ---------------- layernorm (+ optional accumulate) ----------------------
// 8 rows per block, 32 lanes per row, 8 elems per lane.
__global__ void __launch_bounds__(256)
ln_accum_kernel(const float* __restrict__ rst, const float* __restrict__ gamma,
                const float* __restrict__ beta, const float* __restrict__ addin,
                float* __restrict__ out, int M, int do_add) {
    const int row = blockIdx.x * 8 + (threadIdx.x >> 5);
    if (row >= M) return;
    const int lane = threadIdx.x & 31;
    const float4* r4 = (const float4*)(rst + (size_t)row * DD);
    float4 a = r4[lane * 2];
    float4 b = r4[lane * 2 + 1];

    float s = a.x + a.y + a.z + a.w + b.x + b.y + b.z + b.w;
#pragma unroll
    for (int o = 16; o; o >>= 1) s += __shfl_xor_sync(0xFFFFFFFFu, s, o);
    const float mu = s * (1.f / 256.f);

    float d0 = a.x - mu, d1 = a.y - mu, d2 = a.z - mu, d3 = a.w - mu;
    float d4 = b.x - mu, d5 = b.y - mu, d6 = b.z - mu, d7 = b.w - mu;
    float vs = d0 * d0 + d1 * d1 + d2 * d2 + d3 * d3 +
               d4 * d4 + d5 * d5 + d6 * d6 + d7 * d7;
#pragma unroll
    for (int o = 16; o; o >>= 1) vs += __shfl_xor_sync(0xFFFFFFFFu, vs, o);
    const float inv = rsqrtf(vs * (1.f / 256.f) + 1e-5f);

    const float4 g0 = ((const float4*)gamma)[lane * 2];
    const float4 g1 = ((const float4*)gamma)[lane * 2 + 1];
    const float4 e0 = ((const float4*)beta)[lane * 2];
    const float4 e1 = ((const float4*)beta)[lane * 2 + 1];

    float4 y0, y1;
    y0.x = d0 * inv * g0.x + e0.x;
    y0.y = d1 * inv * g0.y + e0.y;
    y0.z = d2 * inv * g0.z + e0.z;
    y0.w = d3 * inv * g0.w + e0.w;
    y1.x = d4 * inv * g1.x + e1.x;
    y1.y = d5 * inv * g1.y + e1.y;
    y1.z = d6 * inv * g1.z + e1.z;
    y1.w = d7 * inv * g1.w + e1.w;

    float4* o4 = (float4*)(out + (size_t)row * DD);
    if (do_add) {
        const float4* ad = (const float4*)(addin + (size_t)row * DD);
        float4 x0 = ad[lane * 2], x1 = ad[lane * 2 + 1];
        y0.x += x0.x; y0.y += x0.y; y0.z += x0.z; y0.w += x0.w;
        y1.x += x1.x; y1.y += x1.y; y1.z += x1.z; y1.w += x1.w;
    }
    o4[lane * 2] = y0;
    o4[lane * 2 + 1] = y1;
}

// ---------------- host orchestration ------------------------------------
extern "C" void kernel_launch(void* const* d_in, const int* in_sizes, int n_in,
                              void* d_out, int out_size) {
    const float* x     = (const float*)d_in[0];   // [N, F]
    const int*   src   = (const int*)d_in[1];     // [T, E]
    const int*   dst   = (const int*)d_in[2];     // [T, E]
    const float* Wlin  = (const float*)d_in[3];   // [D, F]
    const float* blin  = (const float*)d_in[4];   // [D]
    const float* Wpool = (const float*)d_in[5];   // [L, T, D, D]
    const float* bpool = (const float*)d_in[6];   // [L, T, D]
    const float* Wself = (const float*)d_in[7];   // [L, T, D, D]
    const float* Wneigh= (const float*)d_in[8];   // [L, T, D, D]
    const float* bconv = (const float*)d_in[9];   // [L, T, D]
    const float* gamma = (const float*)d_in[10];  // [L, T, D]
    const float* beta  = (const float*)d_in[11];  // [L, T, D]
    float* out = (float*)d_out;                   // [N, D]

    float *ph, *php, *pneigh, *prst, *pout;
    cudaGetSymbolAddress((void**)&ph, g_h);
    cudaGetSymbolAddress((void**)&php, g_hp);
    cudaGetSymbolAddress((void**)&pneigh, g_neigh);
    cudaGetSymbolAddress((void**)&prst, g_rst);
    cudaGetSymbolAddress((void**)&pout, g_out);

    const int M = NN;
    dim3 gemm_grid((M + BM - 1) / BM, DD / BN);  // 157 x 2
    const int scat_blocks = (EE * (DD / 4) + 255) / 256;
    const int ln_blocks = (M + 7) / 8;

    // 1. HeteroLinear: h = x @ Wlin^T + blin
    sgemm_kernel<false, false><<<gemm_grid, 256>>>(
        x, Wlin, nullptr, nullptr, blin, ph, M, FF);

    for (int l = 0; l < LL; ++l) {
        const bool relu = (l < LL - 1);
        for (int t = 0; t < TT; ++t) {
            const int lt = l * TT + t;
            const float* Wp = Wpool + (size_t)lt * DD * DD;
            const float* bp = bpool + (size_t)lt * DD;
            const float* Ws = Wself + (size_t)lt * DD * DD;
            const float* Wn = Wneigh + (size_t)lt * DD * DD;
            const float* bc = bconv + (size_t)lt * DD;
            const float* gm = gamma + (size_t)lt * DD;
            const float* bt = beta + (size_t)lt * DD;
            const int* st = src + (size_t)t * EE;
            const int* dt = dst + (size_t)t * EE;

            // hp = relu(h @ Wpool^T + bpool)
            sgemm_kernel<true, false><<<gemm_grid, 256>>>(
                ph, Wp, nullptr, nullptr, bp, php, M, DD);

            // neigh = segment_max(hp[src], dst)   (zero-init; relu >= 0)
            cudaMemsetAsync(pneigh, 0, (size_t)NN * DD * sizeof(float), 0);
            scatter_max_kernel<<<scat_blocks, 256>>>(st, dt, php, pneigh, EE);

            // rst = h @ Wself^T + neigh @ Wneigh^T + bconv  (+relu if l<L-1)
            if (relu)
                sgemm_kernel<true, true><<<gemm_grid, 256>>>(
                    ph, Ws, pneigh, Wn, bc, prst, M, DD);
            else
                sgemm_kernel<false, true><<<gemm_grid, 256>>>(
                    ph, Ws, pneigh, Wn, bc, prst, M, DD);

            // layernorm; t=0 -> write g_out; t=1 -> add g_out, write next h
            if (t == 0) {
                ln_accum_kernel<<<ln_blocks, 256>>>(
                    prst, gm, bt, nullptr, pout, M, 0);
            } else {
                float* tgt = (l == LL - 1) ? out : ph;
                ln_accum_kernel<<<ln_blocks, 256>>>(
                    prst, gm, bt, pout, tgt, M, 1);
            }
        }
    }
}

// round 3
// speedup vs baseline: 1.9347x; 1.9347x over previous
#include <cuda_runtime.h>
#include <cstdint>

// Problem constants (fixed by the dataset)
#define NN 20000
#define FF 512
#define DD 256
#define EE 200000
#define LL 3
#define TT 2

// ---------------- device scratch (no allocation allowed) ----------------
__device__ float g_h[NN * DD];      // current layer features
__device__ float g_hp[NN * DD];     // relu(h @ Wpool^T + b)
__device__ float g_neigh[NN * DD];  // segment_max result
__device__ float g_rst[NN * DD];    // pre-layernorm result
__device__ float g_out[NN * DD];    // per-layer etype accumulator

// ---------------- tf32 mma.sync GEMM -------------------------------------
// C[M, 256] = A0 @ B0^T (+ A1 @ B1^T) + bias, optional relu.
// A row-major [M, K], B row-major [256, K] (weight layout).
// Block tile 128x128, 8 warps (2x4), warp tile 64x32, BK=32, double buffer.

#define SKS 36                       // smem row stride in words (32 + 4 pad)
#define STAGE_WORDS (128 * SKS)      // one A or B stage
#define SMEM_BYTES (4 * STAGE_WORDS * 4)  // 2 bufs x (A+B) = 73728 B

__device__ __forceinline__ uint32_t f2tf(float f) {
    uint32_t r;
    asm("cvt.rna.tf32.f32 %0, %1;" : "=r"(r) : "f"(f));
    return r;
}

__device__ __forceinline__ void mma8(float* c, const uint32_t* a,
                                     const uint32_t* b) {
    asm volatile(
        "mma.sync.aligned.m16n8k8.row.col.f32.tf32.tf32.f32 "
        "{%0,%1,%2,%3}, {%4,%5,%6,%7}, {%8,%9}, {%0,%1,%2,%3};"
        : "+f"(c[0]), "+f"(c[1]), "+f"(c[2]), "+f"(c[3])
        : "r"(a[0]), "r"(a[1]), "r"(a[2]), "r"(a[3]), "r"(b[0]), "r"(b[1]));
}

template <bool RELU, bool DUAL>
__global__ void __launch_bounds__(256, 1)
mma_gemm(const float* __restrict__ A0, const float* __restrict__ B0,
         const float* __restrict__ A1, const float* __restrict__ B1,
         const float* __restrict__ bias, float* __restrict__ C,
         int M, int K) {
    extern __shared__ uint32_t sm[];
    __shared__ float sBias[128];

    const int tid = threadIdx.x;
    const int brow = blockIdx.x, bcol = blockIdx.y;
    const int warp = tid >> 5, lane = tid & 31;
    const int gid = lane >> 2, tig = lane & 3;
    const int wm = (warp >> 2) * 64;   // warp row offset
    const int wn = (warp & 3) * 32;    // warp col offset

    if (tid < 128) sBias[tid] = bias[bcol * 128 + tid];

    const int sr = tid >> 3;          // 0..31 (staging row group)
    const int sq = (tid & 7) * 4;     // 0,4,...,28 (staging k offset)

    float acc[4][4][4];
#pragma unroll
    for (int mi = 0; mi < 4; ++mi)
#pragma unroll
        for (int ni = 0; ni < 4; ++ni)
#pragma unroll
            for (int j = 0; j < 4; ++j) acc[mi][ni][j] = 0.f;

    const int cpp = K / 32;                  // chunks per pass
    const int nch = DUAL ? 2 * cpp : cpp;

    auto gload = [&](int c, float4* pa, float4* pb) {
        const float* __restrict__ A = (DUAL && c >= cpp) ? A1 : A0;
        const float* __restrict__ B = (DUAL && c >= cpp) ? B1 : B0;
        const int k0 = (DUAL ? (c % cpp) : c) * 32;
#pragma unroll
        for (int i = 0; i < 4; ++i) {
            const int row = sr + 32 * i;
            const int gr = brow * 128 + row;
            pa[i] = (gr < M) ? *(const float4*)(A + (size_t)gr * K + k0 + sq)
                             : make_float4(0.f, 0.f, 0.f, 0.f);
            pb[i] = *(const float4*)(B + (size_t)(bcol * 128 + row) * K + k0 + sq);
        }
    };
    auto stage = [&](const float4* pa, const float4* pb, int buf) {
        uint32_t* As = sm + buf * 2 * STAGE_WORDS;
        uint32_t* Bs = As + STAGE_WORDS;
#pragma unroll
        for (int i = 0; i < 4; ++i) {
            const int row = sr + 32 * i;
            uint4 ta = make_uint4(f2tf(pa[i].x), f2tf(pa[i].y),
                                  f2tf(pa[i].z), f2tf(pa[i].w));
            *(uint4*)&As[row * SKS + sq] = ta;
            uint4 tb = make_uint4(f2tf(pb[i].x), f2tf(pb[i].y),
                                  f2tf(pb[i].z), f2tf(pb[i].w));
            *(uint4*)&Bs[row * SKS + sq] = tb;
        }
    };

    {
        float4 pa[4], pb[4];
        gload(0, pa, pb);
        stage(pa, pb, 0);
    }
    __syncthreads();

    for (int c = 0; c < nch; ++c) {
        const int buf = c & 1;
        const bool more = (c + 1 < nch);
        float4 pa[4], pb[4];
        if (more) gload(c + 1, pa, pb);

        const uint32_t* As = sm + buf * 2 * STAGE_WORDS;
        const uint32_t* Bs = As + STAGE_WORDS;
#pragma unroll
        for (int ks = 0; ks < 4; ++ks) {
            const int kb = ks * 8;
            uint32_t af[4][4], bf[4][2];
#pragma unroll
            for (int mi = 0; mi < 4; ++mi) {
                const int m0 = wm + mi * 16 + gid;
                af[mi][0] = As[m0 * SKS + kb + tig];
                af[mi][1] = As[(m0 + 8) * SKS + kb + tig];
                af[mi][2] = As[m0 * SKS + kb + tig + 4];
                af[mi][3] = As[(m0 + 8) * SKS + kb + tig + 4];
            }
#pragma unroll
            for (int ni = 0; ni < 4; ++ni) {
                const int n0 = wn + ni * 8 + gid;
                bf[ni][0] = Bs[n0 * SKS + kb + tig];
                bf[ni][1] = Bs[n0 * SKS + kb + tig + 4];
            }
#pragma unroll
            for (int mi = 0; mi < 4; ++mi)
#pragma unroll
                for (int ni = 0; ni < 4; ++ni)
                    mma8(acc[mi][ni], af[mi], bf[ni]);
        }
        if (more) {
            __syncthreads();
            stage(pa, pb, buf ^ 1);
            __syncthreads();
        }
    }

    // Epilogue: bias (+relu), store float2 per fragment row pair
#pragma unroll
    for (int mi = 0; mi < 4; ++mi) {
        const int r0 = brow * 128 + wm + mi * 16 + gid;
#pragma unroll
        for (int ni = 0; ni < 4; ++ni) {
            const int lc = wn + ni * 8 + tig * 2;
            const int gc = bcol * 128 + lc;
            float2 v0, v1;
            v0.x = acc[mi][ni][0] + sBias[lc];
            v0.y = acc[mi][ni][1] + sBias[lc + 1];
            v1.x = acc[mi][ni][2] + sBias[lc];
            v1.y = acc[mi][ni][3] + sBias[lc + 1];
            if (RELU) {
                v0.x = fmaxf(v0.x, 0.f); v0.y = fmaxf(v0.y, 0.f);
                v1.x = fmaxf(v1.x, 0.f); v1.y = fmaxf(v1.y, 0.f);
            }
            if (r0 < M)     *(float2*)(C + (size_t)r0 * DD + gc) = v0;
            if (r0 + 8 < M) *(float2*)(C + (size_t)(r0 + 8) * DD + gc) = v1;
        }
    }
}

// ---------------- scatter-max (segment_max with relu-nonneg trick) ------
__global__ void __launch_bounds__(256)
scatter_max_kernel(const int* __restrict__ src, const int* __restrict__ dst,
                   const float* __restrict__ hp, float* __restrict__ neigh,
                   int E) {
    const int idx = blockIdx.x * blockDim.x + threadIdx.x;
    const int total = E * (DD / 4);
    if (idx >= total) return;
    const int e = idx >> 6;        // DD/4 = 64 chunks per edge
    const int c4 = idx & 63;
    const int s = __ldg(src + e);
    const int d = __ldg(dst + e);
    float4 v = *(const float4*)(hp + (size_t)s * DD + c4 * 4);
    unsigned* base = (unsigned*)(neigh + (size_t)d * DD + c4 * 4);
    if (v.x > 0.f) atomicMax(base + 0, __float_as_uint(v.x));
    if (v.y > 0.f) atomicMax(base + 1, __float_as_uint(v.y));
    if (v.z > 0.f) atomicMax(base + 2, __float_as_uint(v.z));
    if (v.w > 0.f) atomicMax(base + 3, __float_as_uint(v.w));
}

// ---------------- layernorm (+ optional accumulate) ----------------------
__global__ void __launch_bounds__(256)
ln_accum_kernel(const float* __restrict__ rst, const float* __restrict__ gamma,
                const float* __restrict__ beta, const float* __restrict__ addin,
                float* __restrict__ out, int M, int do_add) {
    const int row = blockIdx.x * 8 + (threadIdx.x >> 5);
    if (row >= M) return;
    const int lane = threadIdx.x & 31;
    const float4* r4 = (const float4*)(rst + (size_t)row * DD);
    float4 a = r4[lane * 2];
    float4 b = r4[lane * 2 + 1];

    float s = a.x + a.y + a.z + a.w + b.x + b.y + b.z + b.w;
#pragma unroll
    for (int o = 16; o; o >>= 1) s += __shfl_xor_sync(0xFFFFFFFFu, s, o);
    const float mu = s * (1.f / 256.f);

    float d0 = a.x - mu, d1 = a.y - mu, d2 = a.z - mu, d3 = a.w - mu;
    float d4 = b.x - mu, d5 = b.y - mu, d6 = b.z - mu, d7 = b.w - mu;
    float vs = d0 * d0 + d1 * d1 + d2 * d2 + d3 * d3 +
               d4 * d4 + d5 * d5 + d6 * d6 + d7 * d7;
#pragma unroll
    for (int o = 16; o; o >>= 1) vs += __shfl_xor_sync(0xFFFFFFFFu, vs, o);
    const float inv = rsqrtf(vs * (1.f / 256.f) + 1e-5f);

    const float4 g0 = ((const float4*)gamma)[lane * 2];
    const float4 g1 = ((const float4*)gamma)[lane * 2 + 1];
    const float4 e0 = ((const float4*)beta)[lane * 2];
    const float4 e1 = ((const float4*)beta)[lane * 2 + 1];

    float4 y0, y1;
    y0.x = d0 * inv * g0.x + e0.x;
    y0.y = d1 * inv * g0.y + e0.y;
    y0.z = d2 * inv * g0.z + e0.z;
    y0.w = d3 * inv * g0.w + e0.w;
    y1.x = d4 * inv * g1.x + e1.x;
    y1.y = d5 * inv * g1.y + e1.y;
    y1.z = d6 * inv * g1.z + e1.z;
    y1.w = d7 * inv * g1.w + e1.w;

    float4* o4 = (float4*)(out + (size_t)row * DD);
    if (do_add) {
        const float4* ad = (const float4*)(addin + (size_t)row * DD);
        float4 x0 = ad[lane * 2], x1 = ad[lane * 2 + 1];
        y0.x += x0.x; y0.y += x0.y; y0.z += x0.z; y0.w += x0.w;
        y1.x += x1.x; y1.y += x1.y; y1.z += x1.z; y1.w += x1.w;
    }
    o4[lane * 2] = y0;
    o4[lane * 2 + 1] = y1;
}

// ---------------- host orchestration ------------------------------------
extern "C" void kernel_launch(void* const* d_in, const int* in_sizes, int n_in,
                              void* d_out, int out_size) {
    const float* x     = (const float*)d_in[0];   // [N, F]
    const int*   src   = (const int*)d_in[1];     // [T, E]
    const int*   dst   = (const int*)d_in[2];     // [T, E]
    const float* Wlin  = (const float*)d_in[3];   // [D, F]
    const float* blin  = (const float*)d_in[4];   // [D]
    const float* Wpool = (const float*)d_in[5];   // [L, T, D, D]
    const float* bpool = (const float*)d_in[6];   // [L, T, D]
    const float* Wself = (const float*)d_in[7];   // [L, T, D, D]
    const float* Wneigh= (const float*)d_in[8];   // [L, T, D, D]
    const float* bconv = (const float*)d_in[9];   // [L, T, D]
    const float* gamma = (const float*)d_in[10];  // [L, T, D]
    const float* beta  = (const float*)d_in[11];  // [L, T, D]
    float* out = (float*)d_out;                   // [N, D]

    float *ph, *php, *pneigh, *prst, *pout;
    cudaGetSymbolAddress((void**)&ph, g_h);
    cudaGetSymbolAddress((void**)&php, g_hp);
    cudaGetSymbolAddress((void**)&pneigh, g_neigh);
    cudaGetSymbolAddress((void**)&prst, g_rst);
    cudaGetSymbolAddress((void**)&pout, g_out);

    cudaFuncSetAttribute(mma_gemm<false, false>,
                         cudaFuncAttributeMaxDynamicSharedMemorySize, SMEM_BYTES);
    cudaFuncSetAttribute(mma_gemm<true, false>,
                         cudaFuncAttributeMaxDynamicSharedMemorySize, SMEM_BYTES);
    cudaFuncSetAttribute(mma_gemm<true, true>,
                         cudaFuncAttributeMaxDynamicSharedMemorySize, SMEM_BYTES);
    cudaFuncSetAttribute(mma_gemm<false, true>,
                         cudaFuncAttributeMaxDynamicSharedMemorySize, SMEM_BYTES);

    const int M = NN;
    dim3 gemm_grid((M + 127) / 128, 2);   // 157 x 2
    const int scat_blocks = (EE * (DD / 4) + 255) / 256;
    const int ln_blocks = (M + 7) / 8;

    // 1. HeteroLinear: h = x @ Wlin^T + blin
    mma_gemm<false, false><<<gemm_grid, 256, SMEM_BYTES>>>(
        x, Wlin, nullptr, nullptr, blin, ph, M, FF);

    for (int l = 0; l < LL; ++l) {
        const bool relu = (l < LL - 1);
        for (int t = 0; t < TT; ++t) {
            const int lt = l * TT + t;
            const float* Wp = Wpool + (size_t)lt * DD * DD;
            const float* bp = bpool + (size_t)lt * DD;
            const float* Ws = Wself + (size_t)lt * DD * DD;
            const float* Wn = Wneigh + (size_t)lt * DD * DD;
            const float* bc = bconv + (size_t)lt * DD;
            const float* gm = gamma + (size_t)lt * DD;
            const float* bt = beta + (size_t)lt * DD;
            const int* st = src + (size_t)t * EE;
            const int* dt = dst + (size_t)t * EE;

            // hp = relu(h @ Wpool^T + bpool)
            mma_gemm<true, false><<<gemm_grid, 256, SMEM_BYTES>>>(
                ph, Wp, nullptr, nullptr, bp, php, M, DD);

            // neigh = segment_max(hp[src], dst)   (zero-init; relu >= 0)
            cudaMemsetAsync(pneigh, 0, (size_t)NN * DD * sizeof(float), 0);
            scatter_max_kernel<<<scat_blocks, 256>>>(st, dt, php, pneigh, EE);

            // rst = h @ Wself^T + neigh @ Wneigh^T + bconv  (+relu if l<L-1)
            if (relu)
                mma_gemm<true, true><<<gemm_grid, 256, SMEM_BYTES>>>(
                    ph, Ws, pneigh, Wn, bc, prst, M, DD);
            else
                mma_gemm<false, true><<<gemm_grid, 256, SMEM_BYTES>>>(
                    ph, Ws, pneigh, Wn, bc, prst, M, DD);

            // layernorm; t=0 -> write g_out; t=1 -> add g_out, write next h
            if (t == 0) {
                ln_accum_kernel<<<ln_blocks, 256>>>(
                    prst, gm, bt, nullptr, pout, M, 0);
            } else {
                float* tgt = (l == LL - 1) ? out : ph;
                ln_accum_kernel<<<ln_blocks, 256>>>(
                    prst, gm, bt, pout, tgt, M, 1);
            }
        }
    }
}

// round 4
// speedup vs baseline: 2.8228x; 1.4591x over previous
#include <cuda_runtime.h>
#include <cstdint>

// Problem constants (fixed by the dataset)
#define NN 20000
#define FF 512
#define DD 256
#define EE 200000
#define LL 3
#define TT 2

// ---------------- device scratch (no allocation allowed) ----------------
__device__ float g_h[NN * DD];      // current layer features
__device__ float g_hp[NN * DD];     // relu(h @ Wpool^T + b)
__device__ float g_neigh[NN * DD];  // gather-max result
__device__ float g_rst[NN * DD];    // pre-layernorm result
__device__ float g_out[NN * DD];    // per-layer etype accumulator
// CSR (per etype, built once per launch, reused across layers)
__device__ int g_deg[TT][NN];
__device__ int g_rowptr[TT][NN + 1];
__device__ int g_cursor[TT][NN];
__device__ int g_adj[TT][EE];

// ---------------- tf32 mma.sync GEMM -------------------------------------
// C[M, 256] = A0 @ B0^T (+ A1 @ B1^T) + bias, optional relu.
// Block tile 128x128, 8 warps (2x4), warp tile 64x32, BK=32, double buffer.

#define SKS 36                       // smem row stride in words (32 + 4 pad)
#define STAGE_WORDS (128 * SKS)      // one A or B stage
#define SMEM_BYTES (4 * STAGE_WORDS * 4)  // 2 bufs x (A+B) = 73728 B

__device__ __forceinline__ uint32_t f2tf(float f) {
    uint32_t r;
    asm("cvt.rna.tf32.f32 %0, %1;" : "=r"(r) : "f"(f));
    return r;
}

__device__ __forceinline__ void mma8(float* c, const uint32_t* a,
                                     const uint32_t* b) {
    asm volatile(
        "mma.sync.aligned.m16n8k8.row.col.f32.tf32.tf32.f32 "
        "{%0,%1,%2,%3}, {%4,%5,%6,%7}, {%8,%9}, {%0,%1,%2,%3};"
        : "+f"(c[0]), "+f"(c[1]), "+f"(c[2]), "+f"(c[3])
        : "r"(a[0]), "r"(a[1]), "r"(a[2]), "r"(a[3]), "r"(b[0]), "r"(b[1]));
}

template <bool RELU, bool DUAL>
__global__ void __launch_bounds__(256, 1)
mma_gemm(const float* __restrict__ A0, const float* __restrict__ B0,
         const float* __restrict__ A1, const float* __restrict__ B1,
         const float* __restrict__ bias, float* __restrict__ C,
         int M, int K) {
    extern __shared__ uint32_t sm[];
    __shared__ float sBias[128];

    const int tid = threadIdx.x;
    const int brow = blockIdx.x, bcol = blockIdx.y;
    const int warp = tid >> 5, lane = tid & 31;
    const int gid = lane >> 2, tig = lane & 3;
    const int wm = (warp >> 2) * 64;   // warp row offset
    const int wn = (warp & 3) * 32;    // warp col offset

    if (tid < 128) sBias[tid] = bias[bcol * 128 + tid];

    const int sr = tid >> 3;          // 0..31 (staging row group)
    const int sq = (tid & 7) * 4;     // 0,4,...,28 (staging k offset)

    float acc[4][4][4];
#pragma unroll
    for (int mi = 0; mi < 4; ++mi)
#pragma unroll
        for (int ni = 0; ni < 4; ++ni)
#pragma unroll
            for (int j = 0; j < 4; ++j) acc[mi][ni][j] = 0.f;

    const int cpp = K / 32;                  // chunks per pass
    const int nch = DUAL ? 2 * cpp : cpp;

    auto gload = [&](int c, float4* pa, float4* pb) {
        const float* __restrict__ A = (DUAL && c >= cpp) ? A1 : A0;
        const float* __restrict__ B = (DUAL && c >= cpp) ? B1 : B0;
        const int k0 = (DUAL ? (c % cpp) : c) * 32;
#pragma unroll
        for (int i = 0; i < 4; ++i) {
            const int row = sr + 32 * i;
            const int gr = brow * 128 + row;
            pa[i] = (gr < M) ? *(const float4*)(A + (size_t)gr * K + k0 + sq)
                             : make_float4(0.f, 0.f, 0.f, 0.f);
            pb[i] = *(const float4*)(B + (size_t)(bcol * 128 + row) * K + k0 + sq);
        }
    };
    auto stage = [&](const float4* pa, const float4* pb, int buf) {
        uint32_t* As = sm + buf * 2 * STAGE_WORDS;
        uint32_t* Bs = As + STAGE_WORDS;
#pragma unroll
        for (int i = 0; i < 4; ++i) {
            const int row = sr + 32 * i;
            uint4 ta = make_uint4(f2tf(pa[i].x), f2tf(pa[i].y),
                                  f2tf(pa[i].z), f2tf(pa[i].w));
            *(uint4*)&As[row * SKS + sq] = ta;
            uint4 tb = make_uint4(f2tf(pb[i].x), f2tf(pb[i].y),
                                  f2tf(pb[i].z), f2tf(pb[i].w));
            *(uint4*)&Bs[row * SKS + sq] = tb;
        }
    };

    {
        float4 pa[4], pb[4];
        gload(0, pa, pb);
        stage(pa, pb, 0);
    }
    __syncthreads();

    for (int c = 0; c < nch; ++c) {
        const int buf = c & 1;
        const bool more = (c + 1 < nch);
        float4 pa[4], pb[4];
        if (more) gload(c + 1, pa, pb);

        const uint32_t* As = sm + buf * 2 * STAGE_WORDS;
        const uint32_t* Bs = As + STAGE_WORDS;
#pragma unroll
        for (int ks = 0; ks < 4; ++ks) {
            const int kb = ks * 8;
            uint32_t af[4][4], bf[4][2];
#pragma unroll
            for (int mi = 0; mi < 4; ++mi) {
                const int m0 = wm + mi * 16 + gid;
                af[mi][0] = As[m0 * SKS + kb + tig];
                af[mi][1] = As[(m0 + 8) * SKS + kb + tig];
                af[mi][2] = As[m0 * SKS + kb + tig + 4];
                af[mi][3] = As[(m0 + 8) * SKS + kb + tig + 4];
            }
#pragma unroll
            for (int ni = 0; ni < 4; ++ni) {
                const int n0 = wn + ni * 8 + gid;
                bf[ni][0] = Bs[n0 * SKS + kb + tig];
                bf[ni][1] = Bs[n0 * SKS + kb + tig + 4];
            }
#pragma unroll
            for (int mi = 0; mi < 4; ++mi)
#pragma unroll
                for (int ni = 0; ni < 4; ++ni)
                    mma8(acc[mi][ni], af[mi], bf[ni]);
        }
        // Single barrier per chunk: staging buf^1 is WAR-safe because the
        // previous iteration's barrier drained all reads of buf^1.
        if (more) {
            stage(pa, pb, buf ^ 1);
            __syncthreads();
        }
    }

    // Epilogue: bias (+relu), store float2 per fragment row pair
#pragma unroll
    for (int mi = 0; mi < 4; ++mi) {
        const int r0 = brow * 128 + wm + mi * 16 + gid;
#pragma unroll
        for (int ni = 0; ni < 4; ++ni) {
            const int lc = wn + ni * 8 + tig * 2;
            const int gc = bcol * 128 + lc;
            float2 v0, v1;
            v0.x = acc[mi][ni][0] + sBias[lc];
            v0.y = acc[mi][ni][1] + sBias[lc + 1];
            v1.x = acc[mi][ni][2] + sBias[lc];
            v1.y = acc[mi][ni][3] + sBias[lc + 1];
            if (RELU) {
                v0.x = fmaxf(v0.x, 0.f); v0.y = fmaxf(v0.y, 0.f);
                v1.x = fmaxf(v1.x, 0.f); v1.y = fmaxf(v1.y, 0.f);
            }
            if (r0 < M)     *(float2*)(C + (size_t)r0 * DD + gc) = v0;
            if (r0 + 8 < M) *(float2*)(C + (size_t)(r0 + 8) * DD + gc) = v1;
        }
    }
}

// ---------------- CSR build (per etype, once per launch) ----------------
__global__ void hist_kernel(const int* __restrict__ dst, int* __restrict__ deg) {
    const int e = blockIdx.x * blockDim.x + threadIdx.x;
    if (e < EE) atomicAdd(deg + dst[e], 1);
}

// Single-block exclusive scan over NN=20000 degrees; 1024 threads x 20 each.
#define SCAN_PER 20
__global__ void __launch_bounds__(1024)
scan_kernel(const int* __restrict__ deg, int* __restrict__ rowptr,
            int* __restrict__ cursor) {
    __shared__ int warpsum[32];
    const int tid = threadIdx.x;
    const int base = tid * SCAN_PER;
    int local[SCAN_PER];
    int s = 0;
#pragma unroll
    for (int i = 0; i < SCAN_PER; ++i) {
        local[i] = s;
        s += deg[base + i];   // NN == 1024*20 exactly... (20480>20000: guard)
    }
    // NOTE: NN=20000 < 20480, guard handled below via index check on write;
    // reads past NN would be garbage, so re-do with guard:
    // (we recompute safely)
    s = 0;
#pragma unroll
    for (int i = 0; i < SCAN_PER; ++i) {
        const int idx = base + i;
        local[i] = s;
        if (idx < NN) s += deg[idx];
    }
    const int lane = tid & 31, wid = tid >> 5;
    int inc = s;
#pragma unroll
    for (int o = 1; o < 32; o <<= 1) {
        int t = __shfl_up_sync(0xFFFFFFFFu, inc, o);
        if (lane >= o) inc += t;
    }
    if (lane == 31) warpsum[wid] = inc;
    __syncthreads();
    if (wid == 0) {
        int w = warpsum[lane];
#pragma unroll
        for (int o = 1; o < 32; o <<= 1) {
            int t = __shfl_up_sync(0xFFFFFFFFu, w, o);
            if (lane >= o) w += t;
        }
        warpsum[lane] = w;
    }
    __syncthreads();
    const int excl = (inc - s) + (wid > 0 ? warpsum[wid - 1] : 0);
#pragma unroll
    for (int i = 0; i < SCAN_PER; ++i) {
        const int idx = base + i;
        if (idx < NN) {
            const int v = excl + local[i];
            rowptr[idx] = v;
            cursor[idx] = v;
        }
    }
    if (tid == 1023) rowptr[NN] = excl + s;
}

__global__ void fill_kernel(const int* __restrict__ src,
                            const int* __restrict__ dst,
                            int* __restrict__ cursor, int* __restrict__ adj) {
    const int e = blockIdx.x * blockDim.x + threadIdx.x;
    if (e >= EE) return;
    const int p = atomicAdd(cursor + dst[e], 1);
    adj[p] = src[e];
}

// ---------------- gather-max (replaces memset + atomic scatter) ---------
// One thread per (dst, 16B chunk). Warp lanes share the same dst (broadcast
// adj loads); m=0 init implements both zero-in-degree->0 and relu>=0 max.
__global__ void __launch_bounds__(256)
gather_max_kernel(const int* __restrict__ rowptr, const int* __restrict__ adj,
                  const float* __restrict__ hp, float* __restrict__ neigh) {
    const int idx = blockIdx.x * blockDim.x + threadIdx.x;
    const int d = idx >> 6;
    if (d >= NN) return;
    const int c4 = idx & 63;
    const int b = __ldg(rowptr + d), e = __ldg(rowptr + d + 1);
    float4 m = make_float4(0.f, 0.f, 0.f, 0.f);
    int j = b;
    for (; j + 1 < e; j += 2) {
        const int s0 = __ldg(adj + j);
        const int s1 = __ldg(adj + j + 1);
        const float4 v0 = __ldg((const float4*)(hp + (size_t)s0 * DD) + c4);
        const float4 v1 = __ldg((const float4*)(hp + (size_t)s1 * DD) + c4);
        m.x = fmaxf(m.x, fmaxf(v0.x, v1.x));
        m.y = fmaxf(m.y, fmaxf(v0.y, v1.y));
        m.z = fmaxf(m.z, fmaxf(v0.z, v1.z));
        m.w = fmaxf(m.w, fmaxf(v0.w, v1.w));
    }
    if (j < e) {
        const int s0 = __ldg(adj + j);
        const float4 v0 = __ldg((const float4*)(hp + (size_t)s0 * DD) + c4);
        m.x = fmaxf(m.x, v0.x); m.y = fmaxf(m.y, v0.y);
        m.z = fmaxf(m.z, v0.z); m.w = fmaxf(m.w, v0.w);
    }
    *((float4*)(neigh + (size_t)d * DD) + c4) = m;
}

// ---------------- layernorm (+ optional accumulate) ----------------------
__global__ void __launch_bounds__(256)
ln_accum_kernel(const float* __restrict__ rst, const float* __restrict__ gamma,
                const float* __restrict__ beta, const float* __restrict__ addin,
                float* __restrict__ out, int M, int do_add) {
    const int row = blockIdx.x * 8 + (threadIdx.x >> 5);
    if (row >= M) return;
    const int lane = threadIdx.x & 31;
    const float4* r4 = (const float4*)(rst + (size_t)row * DD);
    float4 a = r4[lane * 2];
    float4 b = r4[lane * 2 + 1];

    float s = a.x + a.y + a.z + a.w + b.x + b.y + b.z + b.w;
#pragma unroll
    for (int o = 16; o; o >>= 1) s += __shfl_xor_sync(0xFFFFFFFFu, s, o);
    const float mu = s * (1.f / 256.f);

    float d0 = a.x - mu, d1 = a.y - mu, d2 = a.z - mu, d3 = a.w - mu;
    float d4 = b.x - mu, d5 = b.y - mu, d6 = b.z - mu, d7 = b.w - mu;
    float vs = d0 * d0 + d1 * d1 + d2 * d2 + d3 * d3 +
               d4 * d4 + d5 * d5 + d6 * d6 + d7 * d7;
#pragma unroll
    for (int o = 16; o; o >>= 1) vs += __shfl_xor_sync(0xFFFFFFFFu, vs, o);
    const float inv = rsqrtf(vs * (1.f / 256.f) + 1e-5f);

    const float4 g0 = ((const float4*)gamma)[lane * 2];
    const float4 g1 = ((const float4*)gamma)[lane * 2 + 1];
    const float4 e0 = ((const float4*)beta)[lane * 2];
    const float4 e1 = ((const float4*)beta)[lane * 2 + 1];

    float4 y0, y1;
    y0.x = d0 * inv * g0.x + e0.x;
    y0.y = d1 * inv * g0.y + e0.y;
    y0.z = d2 * inv * g0.z + e0.z;
    y0.w = d3 * inv * g0.w + e0.w;
    y1.x = d4 * inv * g1.x + e1.x;
    y1.y = d5 * inv * g1.y + e1.y;
    y1.z = d6 * inv * g1.z + e1.z;
    y1.w = d7 * inv * g1.w + e1.w;

    float4* o4 = (float4*)(out + (size_t)row * DD);
    if (do_add) {
        const float4* ad = (const float4*)(addin + (size_t)row * DD);
        float4 x0 = ad[lane * 2], x1 = ad[lane * 2 + 1];
        y0.x += x0.x; y0.y += x0.y; y0.z += x0.z; y0.w += x0.w;
        y1.x += x1.x; y1.y += x1.y; y1.z += x1.z; y1.w += x1.w;
    }
    o4[lane * 2] = y0;
    o4[lane * 2 + 1] = y1;
}

// ---------------- host orchestration ------------------------------------
extern "C" void kernel_launch(void* const* d_in, const int* in_sizes, int n_in,
                              void* d_out, int out_size) {
    const float* x     = (const float*)d_in[0];   // [N, F]
    const int*   src   = (const int*)d_in[1];     // [T, E]
    const int*   dst   = (const int*)d_in[2];     // [T, E]
    const float* Wlin  = (const float*)d_in[3];   // [D, F]
    const float* blin  = (const float*)d_in[4];   // [D]
    const float* Wpool = (const float*)d_in[5];   // [L, T, D, D]
    const float* bpool = (const float*)d_in[6];   // [L, T, D]
    const float* Wself = (const float*)d_in[7];   // [L, T, D, D]
    const float* Wneigh= (const float*)d_in[8];   // [L, T, D, D]
    const float* bconv = (const float*)d_in[9];   // [L, T, D]
    const float* gamma = (const float*)d_in[10];  // [L, T, D]
    const float* beta  = (const float*)d_in[11];  // [L, T, D]
    float* out = (float*)d_out;                   // [N, D]

    float *ph, *php, *pneigh, *prst, *pout;
    int *pdeg, *prow, *pcur, *padj;
    cudaGetSymbolAddress((void**)&ph, g_h);
    cudaGetSymbolAddress((void**)&php, g_hp);
    cudaGetSymbolAddress((void**)&pneigh, g_neigh);
    cudaGetSymbolAddress((void**)&prst, g_rst);
    cudaGetSymbolAddress((void**)&pout, g_out);
    cudaGetSymbolAddress((void**)&pdeg, g_deg);
    cudaGetSymbolAddress((void**)&prow, g_rowptr);
    cudaGetSymbolAddress((void**)&pcur, g_cursor);
    cudaGetSymbolAddress((void**)&padj, g_adj);

    cudaFuncSetAttribute(mma_gemm<false, false>,
                         cudaFuncAttributeMaxDynamicSharedMemorySize, SMEM_BYTES);
    cudaFuncSetAttribute(mma_gemm<true, false>,
                         cudaFuncAttributeMaxDynamicSharedMemorySize, SMEM_BYTES);
    cudaFuncSetAttribute(mma_gemm<true, true>,
                         cudaFuncAttributeMaxDynamicSharedMemorySize, SMEM_BYTES);
    cudaFuncSetAttribute(mma_gemm<false, true>,
                         cudaFuncAttributeMaxDynamicSharedMemorySize, SMEM_BYTES);

    const int M = NN;
    dim3 gemm_grid((M + 127) / 128, 2);   // 157 x 2
    const int eblocks = (EE + 255) / 256;
    const int gblocks = (NN * 64 + 255) / 256;
    const int ln_blocks = (M + 7) / 8;

    // Build CSR for both etypes (reused across all 3 layers)
    cudaMemsetAsync(pdeg, 0, sizeof(int) * TT * NN, 0);
    for (int t = 0; t < TT; ++t) {
        const int* st = src + (size_t)t * EE;
        const int* dt = dst + (size_t)t * EE;
        hist_kernel<<<eblocks, 256>>>(dt, pdeg + t * NN);
        scan_kernel<<<1, 1024>>>(pdeg + t * NN, prow + t * (NN + 1), pcur + t * NN);
        fill_kernel<<<eblocks, 256>>>(st, dt, pcur + t * NN, padj + t * EE);
    }

    // 1. HeteroLinear: h = x @ Wlin^T + blin
    mma_gemm<false, false><<<gemm_grid, 256, SMEM_BYTES>>>(
        x, Wlin, nullptr, nullptr, blin, ph, M, FF);

    for (int l = 0; l < LL; ++l) {
        const bool relu = (l < LL - 1);
        for (int t = 0; t < TT; ++t) {
            const int lt = l * TT + t;
            const float* Wp = Wpool + (size_t)lt * DD * DD;
            const float* bp = bpool + (size_t)lt * DD;
            const float* Ws = Wself + (size_t)lt * DD * DD;
            const float* Wn = Wneigh + (size_t)lt * DD * DD;
            const float* bc = bconv + (size_t)lt * DD;
            const float* gm = gamma + (size_t)lt * DD;
            const float* bt = beta + (size_t)lt * DD;

            // hp = relu(h @ Wpool^T + bpool)
            mma_gemm<true, false><<<gemm_grid, 256, SMEM_BYTES>>>(
                ph, Wp, nullptr, nullptr, bp, php, M, DD);

            // neigh[d] = max over in-edges of hp[src] (0 if no edges)
            gather_max_kernel<<<gblocks, 256>>>(
                prow + t * (NN + 1), padj + t * EE, php, pneigh);

            // rst = h @ Wself^T + neigh @ Wneigh^T + bconv  (+relu if l<L-1)
            if (relu)
                mma_gemm<true, true><<<gemm_grid, 256, SMEM_BYTES>>>(
                    ph, Ws, pneigh, Wn, bc, prst, M, DD);
            else
                mma_gemm<false, true><<<gemm_grid, 256, SMEM_BYTES>>>(
                    ph, Ws, pneigh, Wn, bc, prst, M, DD);

            // layernorm; t=0 -> write g_out; t=1 -> add g_out, write next h
            if (t == 0) {
                ln_accum_kernel<<<ln_blocks, 256>>>(
                    prst, gm, bt, nullptr, pout, M, 0);
            } else {
                float* tgt = (l == LL - 1) ? out : ph;
                ln_accum_kernel<<<ln_blocks, 256>>>(
                    prst, gm, bt, pout, tgt, M, 1);
            }
        }
    }
}